// round 8
// baseline (speedup 1.0000x reference)
#include <cuda_runtime.h>
#include <cuda_bf16.h>
#include <cstdint>

#define N_NODES 65536
#define E_EDGES 1048576
#define IN_DIM  500
#define HID     256
#define OUT_DIM 64
#define ALPHA_C 0.1f
#define K_STEPS 10

// ======================= helpers =======================
__device__ __forceinline__ uint32_t smem_u32(const void* p) {
    uint32_t a;
    asm("{ .reg .u64 t; cvta.to.shared.u64 t, %1; cvt.u32.u64 %0, t; }" : "=r"(a) : "l"(p));
    return a;
}
#define CP_ASYNC16(dst, src) \
    asm volatile("cp.async.cg.shared.global [%0], [%1], 16;" :: "r"(dst), "l"(src) : "memory")
#define CP_COMMIT()  asm volatile("cp.async.commit_group;" ::: "memory")
#define CP_WAIT(n)   asm volatile("cp.async.wait_group %0;" :: "n"(n) : "memory")

#define LDMATRIX_X4(r0, r1, r2, r3, addr) \
    asm volatile("ldmatrix.sync.aligned.m8n8.x4.shared.b16 {%0,%1,%2,%3}, [%4];" \
        : "=r"(r0), "=r"(r1), "=r"(r2), "=r"(r3) : "r"(addr))

#define MMA_16816(d, a0, a1, a2, a3, b0, b1) \
    asm volatile("mma.sync.aligned.m16n8k16.row.col.f32.bf16.bf16.f32 " \
        "{%0,%1,%2,%3}, {%4,%5,%6,%7}, {%8,%9}, {%0,%1,%2,%3};" \
        : "+f"((d)[0]), "+f"((d)[1]), "+f"((d)[2]), "+f"((d)[3]) \
        : "r"(a0), "r"(a1), "r"(a2), "r"(a3), "r"(b0), "r"(b1))

// ======================= device scratch (no allocs) =======================
__device__ __align__(256) __nv_bfloat16 g_x2[(size_t)N_NODES * 1024];  // hi cols 0..511, lo 512..1023
__device__ __align__(256) __nv_bfloat16 g_h1s[(size_t)N_NODES * 512];  // hi 0..255, lo 256..511
__device__ __align__(256) __nv_bfloat16 g_h2s[(size_t)N_NODES * 512];
__device__ __align__(256) float g_h0[(size_t)N_NODES * OUT_DIM];
__device__ __align__(256) float g_ha[(size_t)N_NODES * OUT_DIM];
__device__ __align__(256) __nv_bfloat16 g_B1h[256 * 512], g_B1l[256 * 512];  // [N, Kpad]
__device__ __align__(256) __nv_bfloat16 g_B2h[256 * 256], g_B2l[256 * 256];
__device__ __align__(256) __nv_bfloat16 g_B3h[64 * 256],  g_B3l[64 * 256];
__device__ int   g_deg[N_NODES];
__device__ int   g_cur[N_NODES];
__device__ int   g_off[N_NODES + 1];
__device__ int   g_bsum[64];
__device__ int   g_boff[64];
__device__ __align__(16) int2 g_edges[E_EDGES + N_NODES];   // even-padded CSR

// ======================= bf16 split conversion =======================
__device__ __forceinline__ void split_bf16(float v, __nv_bfloat16& hi, __nv_bfloat16& lo) {
    hi = __float2bfloat16_rn(v);
    lo = __float2bfloat16_rn(v - __bfloat162float(hi));
}

// x [65536, 500] f32 -> g_x2 [65536, 1024] split-bf16 (K padded to 512)
__global__ void conv_x_kernel(const float* __restrict__ x) {
    int t = blockIdx.x * blockDim.x + threadIdx.x;   // N_NODES*64 threads
    int row = t >> 6;
    int k8  = (t & 63) * 8;
    float4 v0 = make_float4(0.f, 0.f, 0.f, 0.f);
    float4 v1 = make_float4(0.f, 0.f, 0.f, 0.f);
    if (k8 + 3 < IN_DIM) v0 = *(const float4*)(x + (size_t)row * IN_DIM + k8);
    if (k8 + 7 < IN_DIM) v1 = *(const float4*)(x + (size_t)row * IN_DIM + k8 + 4);
    __align__(16) __nv_bfloat16 h[8], l[8];
    split_bf16(v0.x, h[0], l[0]); split_bf16(v0.y, h[1], l[1]);
    split_bf16(v0.z, h[2], l[2]); split_bf16(v0.w, h[3], l[3]);
    split_bf16(v1.x, h[4], l[4]); split_bf16(v1.y, h[5], l[5]);
    split_bf16(v1.z, h[6], l[6]); split_bf16(v1.w, h[7], l[7]);
    size_t o = (size_t)row * 1024 + k8;
    *(uint4*)(g_x2 + o)       = *(uint4*)h;
    *(uint4*)(g_x2 + o + 512) = *(uint4*)l;
}

__device__ __forceinline__ void conv_w_one(const float* __restrict__ W,
                                           __nv_bfloat16* __restrict__ Bh,
                                           __nv_bfloat16* __restrict__ Bl,
                                           int t, int K, int N, int Kpad) {
    int n = t / Kpad, k = t % Kpad;
    float w = (k < K) ? W[(size_t)k * N + n] : 0.f;
    __nv_bfloat16 hi, lo;
    split_bf16(w, hi, lo);
    Bh[t] = hi; Bl[t] = lo;
}
__global__ void conv_w_all_kernel(const float* __restrict__ W1,
                                  const float* __restrict__ W2,
                                  const float* __restrict__ W3) {
    int t = blockIdx.x * blockDim.x + threadIdx.x;
    if (t < 131072)        conv_w_one(W1, g_B1h, g_B1l, t,          IN_DIM, HID,    512);
    else if (t < 196608)   conv_w_one(W2, g_B2h, g_B2l, t - 131072, HID,    HID,    256);
    else if (t < 212992)   conv_w_one(W3, g_B3h, g_B3l, t - 196608, HID,    OUT_DIM, 256);
}

// ======================= HMMA split-bf16 GEMM =======================
// BM=256, 8 warps in 4x2 -> 64x64 warp tiles (64x32 for BN=64).
template <int BN, int K_SEG, int A_STRIDE, bool RELU, bool SPLIT_OUT, int N_FULL>
__global__ void __launch_bounds__(256) mma_gemm_kernel(
    const __nv_bfloat16* __restrict__ A,
    const __nv_bfloat16* __restrict__ Bh,
    const __nv_bfloat16* __restrict__ Bl,
    const float* __restrict__ bias,
    void* __restrict__ outp)
{
    constexpr int BM = 256, BK = 64;
    constexpr int CPS = K_SEG / BK;
    constexpr int NCH = 3 * CPS;
    constexpr int A_BYTES = BM * 128;
    constexpr int B_BYTES = BN * 128;
    constexpr int STAGE = A_BYTES + B_BYTES;
    constexpr int WARP_N = BN / 2;
    constexpr int NB = WARP_N / 8;

    extern __shared__ char smem[];
    const uint32_t smem_b = smem_u32(smem);
    const int tid = threadIdx.x;
    const int wid = tid >> 5, lane = tid & 31;
    const int row0 = blockIdx.y * BM;
    const int col0 = blockIdx.x * BN;
    const int wm = (wid & 3) * 64;
    const int wn = (wid >> 2) * WARP_N;

    float acc[4][NB][4];
    #pragma unroll
    for (int mi = 0; mi < 4; mi++)
        #pragma unroll
        for (int ni = 0; ni < NB; ni++)
            #pragma unroll
            for (int q = 0; q < 4; q++) acc[mi][ni][q] = 0.f;

    auto issue_load = [&](int c, int buf) {
        int seg = c / CPS;
        int kk  = (c % CPS) * BK;
        const __nv_bfloat16* Asrc = A + (seg == 2 ? A_STRIDE / 2 : 0) + kk;
        const __nv_bfloat16* Bsrc = (seg == 1 ? Bl : Bh) + kk;
        uint32_t sa = smem_b + buf * STAGE;
        uint32_t sb = sa + A_BYTES;
        #pragma unroll
        for (int i = 0; i < 8; i++) {                 // A: 2048 x 16B
            int idx = tid + i * 256;
            int r = idx >> 3, c8 = idx & 7;
            const void* g = Asrc + (size_t)(row0 + r) * A_STRIDE + c8 * 8;
            CP_ASYNC16(sa + (uint32_t)(r * 128 + ((c8 * 16) ^ ((r & 7) * 16))), g);
        }
        #pragma unroll
        for (int i = 0; i < BN / 32; i++) {
            int idx = tid + i * 256;
            int r = idx >> 3, c8 = idx & 7;
            const void* g = Bsrc + (size_t)(col0 + r) * K_SEG + c8 * 8;
            CP_ASYNC16(sb + (uint32_t)(r * 128 + ((c8 * 16) ^ ((r & 7) * 16))), g);
        }
        CP_COMMIT();
    };

    const int a_r7  = lane & 7;
    const int a_m8  = ((lane >> 3) & 1) * 8;
    const int a_cb  = ((lane >> 4) & 1) * 16;
    const int a_xor = a_r7 * 16;
    const int b_r7  = lane & 7;
    const int b_n8  = ((lane >> 4) & 1) * 8;
    const int b_cb  = ((lane >> 3) & 1) * 16;
    const int b_xor = b_r7 * 16;

    issue_load(0, 0);
    issue_load(1, 1);

    int buf = 0;
    for (int c = 0; c < NCH; c++) {
        CP_WAIT(1);
        __syncthreads();
        if (c + 2 < NCH) issue_load(c + 2, (c + 2) % 3);
        else             CP_COMMIT();

        const uint32_t sa = smem_b + buf * STAGE;
        const uint32_t sb = sa + A_BYTES;
        const uint32_t a_base = sa + (uint32_t)((wm + a_r7 + a_m8) * 128);
        const uint32_t b_base = sb + (uint32_t)((wn + b_r7 + b_n8) * 128);

        #pragma unroll
        for (int k16 = 0; k16 < 4; k16++) {
            const int kb = k16 * 32;
            uint32_t Af[4][4];
            #pragma unroll
            for (int m = 0; m < 4; m++)
                LDMATRIX_X4(Af[m][0], Af[m][1], Af[m][2], Af[m][3],
                            a_base + (uint32_t)(m * 2048) + ((kb + a_cb) ^ a_xor));
            #pragma unroll
            for (int j = 0; j < NB / 2; j++) {
                uint32_t B4[4];
                LDMATRIX_X4(B4[0], B4[1], B4[2], B4[3],
                            b_base + (uint32_t)(j * 2048) + ((kb + b_cb) ^ b_xor));
                #pragma unroll
                for (int m = 0; m < 4; m++) {
                    MMA_16816(acc[m][2 * j + 0], Af[m][0], Af[m][1], Af[m][2], Af[m][3], B4[0], B4[1]);
                    MMA_16816(acc[m][2 * j + 1], Af[m][0], Af[m][1], Af[m][2], Af[m][3], B4[2], B4[3]);
                }
            }
        }
        buf = (buf + 1 == 3) ? 0 : buf + 1;
    }

    const int qrow = lane >> 2;
    const int qcol = (lane & 3) * 2;
    #pragma unroll
    for (int mi = 0; mi < 4; mi++) {
        #pragma unroll
        for (int ni = 0; ni < NB; ni++) {
            const int col = col0 + wn + ni * 8 + qcol;
            const float bv0 = __ldg(bias + col);
            const float bv1 = __ldg(bias + col + 1);
            #pragma unroll
            for (int h = 0; h < 2; h++) {
                const int row = row0 + wm + mi * 16 + qrow + h * 8;
                float v0 = acc[mi][ni][h * 2 + 0] + bv0;
                float v1 = acc[mi][ni][h * 2 + 1] + bv1;
                if (RELU) { v0 = fmaxf(v0, 0.f); v1 = fmaxf(v1, 0.f); }
                if (SPLIT_OUT) {
                    __nv_bfloat16* outb = (__nv_bfloat16*)outp;
                    __nv_bfloat162 hi, lo;
                    split_bf16(v0, hi.x, lo.x);
                    split_bf16(v1, hi.y, lo.y);
                    size_t o = (size_t)row * (2 * N_FULL);
                    *(__nv_bfloat162*)(outb + o + col)          = hi;
                    *(__nv_bfloat162*)(outb + o + N_FULL + col) = lo;
                } else {
                    float* outf = (float*)outp;
                    float2 v = make_float2(v0, v1);
                    *(float2*)(outf + (size_t)row * N_FULL + col) = v;
                }
            }
        }
    }
}

// ======================= CSR build (side stream, even-padded degrees) =======================
__global__ void zero_counts_kernel() {
    int i = blockIdx.x * blockDim.x + threadIdx.x;
    if (i < N_NODES) { g_deg[i] = 0; g_cur[i] = 0; }
}
__global__ void count_deg_kernel(const int* __restrict__ erow) {
    int e = blockIdx.x * blockDim.x + threadIdx.x;
    if (e < E_EDGES) atomicAdd(&g_deg[erow[e]], 1);
}
__global__ void scan1_kernel() {      // scan over degrees padded to even
    __shared__ int wsums[32];
    const int tid = threadIdx.x;
    const int i = blockIdx.x * 1024 + tid;
    const int v = (g_deg[i] + 1) & ~1;
    int x = v;
    #pragma unroll
    for (int o = 1; o < 32; o <<= 1) {
        int t = __shfl_up_sync(0xFFFFFFFFu, x, o);
        if ((tid & 31) >= o) x += t;
    }
    if ((tid & 31) == 31) wsums[tid >> 5] = x;
    __syncthreads();
    if (tid < 32) {
        int y = wsums[tid];
        #pragma unroll
        for (int o = 1; o < 32; o <<= 1) {
            int t = __shfl_up_sync(0xFFFFFFFFu, y, o);
            if (tid >= o) y += t;
        }
        wsums[tid] = y;
    }
    __syncthreads();
    const int warp = tid >> 5;
    const int base = warp ? wsums[warp - 1] : 0;
    g_off[i] = base + x - v;
    if (tid == 1023) g_bsum[blockIdx.x] = wsums[31];
}
__global__ void scan2_kernel() {   // 1 block, 64 threads
    __shared__ int s0;
    const int tid = threadIdx.x;
    const int v = g_bsum[tid];
    int x = v;
    #pragma unroll
    for (int o = 1; o < 32; o <<= 1) {
        int t = __shfl_up_sync(0xFFFFFFFFu, x, o);
        if ((tid & 31) >= o) x += t;
    }
    if (tid == 31) s0 = x;
    __syncthreads();
    const int add = (tid >= 32) ? s0 : 0;
    g_boff[tid] = add + x - v;
}
__global__ void scan3_kernel() {   // 64 blocks x 1024
    const int i = blockIdx.x * 1024 + threadIdx.x;
    const int o = g_off[i] + g_boff[blockIdx.x];
    g_off[i] = o;
    if (i == N_NODES - 1) g_off[N_NODES] = o + ((g_deg[i] + 1) & ~1);
}
__global__ void pad_fill_kernel() {   // zero filler slot for odd-degree nodes
    const int i = blockIdx.x * blockDim.x + threadIdx.x;
    if (i < N_NODES) {
        const int d = g_deg[i];
        if (d & 1) g_edges[g_off[i] + d] = make_int2(0, 0);
    }
}
__global__ void fill_csr_kernel(const int* __restrict__ erow,
                                const int* __restrict__ ecol,
                                const float* __restrict__ ew) {
    int e = blockIdx.x * blockDim.x + threadIdx.x;
    if (e < E_EDGES) {
        int r = erow[e];
        int p = g_off[r] + atomicAdd(&g_cur[r], 1);
        g_edges[p] = make_int2(ecol[e], __float_as_int(0.9f * ew[e]));
    }
}

// ======================= propagation (one warp per node, paired edges) =======================
__global__ void prop_kernel(const float* __restrict__ src,
                            const float* __restrict__ h0,
                            float* __restrict__ dst) {
    const int gw   = (blockIdx.x * blockDim.x + threadIdx.x) >> 5;
    const int lane = threadIdx.x & 31;
    if (gw >= N_NODES) return;
    const int s = g_off[gw];        // even
    const int e = g_off[gw + 1];    // even
    const int half = lane >> 4;
    const int fq   = lane & 15;

    float4 a = make_float4(0.f, 0.f, 0.f, 0.f);
    for (int i = s; i < e; i += 2) {
        const int4 ep = __ldg((const int4*)(g_edges + i));   // 2 edges, 16B aligned
        const int   col = half ? ep.z : ep.x;
        const float w   = __int_as_float(half ? ep.w : ep.y);
        const float4 v  = __ldg((const float4*)(src + ((size_t)col << 6)) + fq);
        a.x = fmaf(w, v.x, a.x);
        a.y = fmaf(w, v.y, a.y);
        a.z = fmaf(w, v.z, a.z);
        a.w = fmaf(w, v.w, a.w);
    }
    a.x += __shfl_xor_sync(0xFFFFFFFFu, a.x, 16);
    a.y += __shfl_xor_sync(0xFFFFFFFFu, a.y, 16);
    a.z += __shfl_xor_sync(0xFFFFFFFFu, a.z, 16);
    a.w += __shfl_xor_sync(0xFFFFFFFFu, a.w, 16);
    if (lane < 16) {
        const float4 hv = __ldg((const float4*)(h0 + ((size_t)gw << 6)) + fq);
        float4 o;
        o.x = fmaf(ALPHA_C, hv.x, a.x);
        o.y = fmaf(ALPHA_C, hv.y, a.y);
        o.z = fmaf(ALPHA_C, hv.z, a.z);
        o.w = fmaf(ALPHA_C, hv.w, a.w);
        ((float4*)(dst + ((size_t)gw << 6)))[fq] = o;
    }
}

// ======================= launch =======================
extern "C" void kernel_launch(void* const* d_in, const int* in_sizes, int n_in,
                              void* d_out, int out_size) {
    const float* x  = (const float*)d_in[0];
    const float* W1 = (const float*)d_in[1];
    const float* b1 = (const float*)d_in[2];
    const float* W2 = (const float*)d_in[3];
    const float* b2 = (const float*)d_in[4];
    const float* W3 = (const float*)d_in[5];
    const float* b3 = (const float*)d_in[6];
    const float* ew = (const float*)d_in[7];
    const int*   er = (const int*)d_in[8];
    const int*   ec = (const int*)d_in[9];
    float* out = (float*)d_out;

    float *h0, *ha;
    __nv_bfloat16 *x2, *h1s, *h2s, *B1h, *B1l, *B2h, *B2l, *B3h, *B3l;
    cudaGetSymbolAddress((void**)&h0,  g_h0);
    cudaGetSymbolAddress((void**)&ha,  g_ha);
    cudaGetSymbolAddress((void**)&x2,  g_x2);
    cudaGetSymbolAddress((void**)&h1s, g_h1s);
    cudaGetSymbolAddress((void**)&h2s, g_h2s);
    cudaGetSymbolAddress((void**)&B1h, g_B1h);
    cudaGetSymbolAddress((void**)&B1l, g_B1l);
    cudaGetSymbolAddress((void**)&B2h, g_B2h);
    cudaGetSymbolAddress((void**)&B2l, g_B2l);
    cudaGetSymbolAddress((void**)&B3h, g_B3h);
    cudaGetSymbolAddress((void**)&B3l, g_B3l);

    constexpr int SMEM_BN128 = 3 * (256 * 128 + 128 * 128);  // 147456
    constexpr int SMEM_BN64  = 3 * (256 * 128 + 64 * 128);   // 122880

    static cudaStream_t s2;
    static cudaEvent_t evF, evJ;
    static bool inited = false;
    if (!inited) {
        cudaStreamCreateWithFlags(&s2, cudaStreamNonBlocking);
        cudaEventCreateWithFlags(&evF, cudaEventDisableTiming);
        cudaEventCreateWithFlags(&evJ, cudaEventDisableTiming);
        cudaFuncSetAttribute(mma_gemm_kernel<128, 512, 1024, true,  true,  256>,
                             cudaFuncAttributeMaxDynamicSharedMemorySize, SMEM_BN128);
        cudaFuncSetAttribute(mma_gemm_kernel<128, 256, 512,  true,  true,  256>,
                             cudaFuncAttributeMaxDynamicSharedMemorySize, SMEM_BN128);
        cudaFuncSetAttribute(mma_gemm_kernel<64,  256, 512,  false, false, 64>,
                             cudaFuncAttributeMaxDynamicSharedMemorySize, SMEM_BN64);
        inited = true;
    }

    // ---- fork: CSR chain on side stream, overlapped with conv + GEMMs ----
    cudaEventRecord(evF, 0);
    cudaStreamWaitEvent(s2, evF, 0);

    zero_counts_kernel<<<N_NODES / 256, 256, 0, s2>>>();
    count_deg_kernel<<<E_EDGES / 256, 256, 0, s2>>>(er);
    scan1_kernel<<<64, 1024, 0, s2>>>();
    scan2_kernel<<<1, 64, 0, s2>>>();
    scan3_kernel<<<64, 1024, 0, s2>>>();
    pad_fill_kernel<<<N_NODES / 256, 256, 0, s2>>>();
    fill_csr_kernel<<<E_EDGES / 256, 256, 0, s2>>>(er, ec, ew);
    cudaEventRecord(evJ, s2);

    // ---- main stream: conversions + MLP ----
    conv_x_kernel<<<(N_NODES * 64) / 256, 256>>>(x);
    conv_w_all_kernel<<<(212992 + 255) / 256, 256>>>(W1, W2, W3);

    mma_gemm_kernel<128, 512, 1024, true,  true,  256>
        <<<dim3(2, N_NODES / 256), 256, SMEM_BN128>>>(x2,  B1h, B1l, b1, h1s);
    mma_gemm_kernel<128, 256, 512,  true,  true,  256>
        <<<dim3(2, N_NODES / 256), 256, SMEM_BN128>>>(h1s, B2h, B2l, b2, h2s);
    mma_gemm_kernel<64,  256, 512,  false, false, 64>
        <<<dim3(1, N_NODES / 256), 256, SMEM_BN64>>>(h2s, B3h, B3l, b3, h0);

    // ---- join, then K=10 propagation steps (one warp per node) ----
    cudaStreamWaitEvent(0, evJ, 0);
    const float* src = h0;
    for (int s = 0; s < K_STEPS; s++) {
        float* dst = (s % 2 == 0) ? ha : out;
        prop_kernel<<<N_NODES / 8, 256>>>(src, h0, dst);
        src = dst;
    }
}

// round 9
// speedup vs baseline: 1.0958x; 1.0958x over previous
#include <cuda_runtime.h>
#include <cuda_bf16.h>
#include <cstdint>

#define N_NODES 65536
#define E_EDGES 1048576
#define IN_DIM  500
#define HID     256
#define OUT_DIM 64
#define ALPHA_C 0.1f
#define K_STEPS 10

// ======================= helpers =======================
__device__ __forceinline__ uint32_t smem_u32(const void* p) {
    uint32_t a;
    asm("{ .reg .u64 t; cvta.to.shared.u64 t, %1; cvt.u32.u64 %0, t; }" : "=r"(a) : "l"(p));
    return a;
}
#define CP_ASYNC16(dst, src) \
    asm volatile("cp.async.cg.shared.global [%0], [%1], 16;" :: "r"(dst), "l"(src) : "memory")
#define CP_COMMIT()  asm volatile("cp.async.commit_group;" ::: "memory")
#define CP_WAIT(n)   asm volatile("cp.async.wait_group %0;" :: "n"(n) : "memory")

#define LDMATRIX_X4(r0, r1, r2, r3, addr) \
    asm volatile("ldmatrix.sync.aligned.m8n8.x4.shared.b16 {%0,%1,%2,%3}, [%4];" \
        : "=r"(r0), "=r"(r1), "=r"(r2), "=r"(r3) : "r"(addr))

#define MMA_16816(d, a0, a1, a2, a3, b0, b1) \
    asm volatile("mma.sync.aligned.m16n8k16.row.col.f32.bf16.bf16.f32 " \
        "{%0,%1,%2,%3}, {%4,%5,%6,%7}, {%8,%9}, {%0,%1,%2,%3};" \
        : "+f"((d)[0]), "+f"((d)[1]), "+f"((d)[2]), "+f"((d)[3]) \
        : "r"(a0), "r"(a1), "r"(a2), "r"(a3), "r"(b0), "r"(b1))

// ======================= device scratch (no allocs) =======================
__device__ __align__(256) __nv_bfloat16 g_x2[(size_t)N_NODES * 1024];  // hi cols 0..511, lo 512..1023
__device__ __align__(256) __nv_bfloat16 g_h1s[(size_t)N_NODES * 512];  // hi 0..255, lo 256..511
__device__ __align__(256) __nv_bfloat16 g_h2s[(size_t)N_NODES * 512];
__device__ __align__(256) float g_h0[(size_t)N_NODES * OUT_DIM];
__device__ __align__(256) float g_ha[(size_t)N_NODES * OUT_DIM];
__device__ __align__(256) __nv_bfloat16 g_B1h[256 * 512], g_B1l[256 * 512];  // [N, Kpad]
__device__ __align__(256) __nv_bfloat16 g_B2h[256 * 256], g_B2l[256 * 256];
__device__ __align__(256) __nv_bfloat16 g_B3h[64 * 256],  g_B3l[64 * 256];
__device__ int   g_deg[N_NODES];
__device__ int   g_cur[N_NODES];
__device__ int   g_off[N_NODES + 1];
__device__ int   g_bsum[64];
__device__ int   g_boff[64];
__device__ __align__(16) int2 g_edges[E_EDGES + N_NODES];   // even-padded CSR

// ======================= bf16 split conversion =======================
__device__ __forceinline__ void split_bf16(float v, __nv_bfloat16& hi, __nv_bfloat16& lo) {
    hi = __float2bfloat16_rn(v);
    lo = __float2bfloat16_rn(v - __bfloat162float(hi));
}

// x [65536, 500] f32 -> g_x2 [65536, 1024] split-bf16 (K padded to 512)
__global__ void conv_x_kernel(const float* __restrict__ x) {
    int t = blockIdx.x * blockDim.x + threadIdx.x;   // N_NODES*64 threads
    int row = t >> 6;
    int k8  = (t & 63) * 8;
    float4 v0 = make_float4(0.f, 0.f, 0.f, 0.f);
    float4 v1 = make_float4(0.f, 0.f, 0.f, 0.f);
    if (k8 + 3 < IN_DIM) v0 = *(const float4*)(x + (size_t)row * IN_DIM + k8);
    if (k8 + 7 < IN_DIM) v1 = *(const float4*)(x + (size_t)row * IN_DIM + k8 + 4);
    __align__(16) __nv_bfloat16 h[8], l[8];
    split_bf16(v0.x, h[0], l[0]); split_bf16(v0.y, h[1], l[1]);
    split_bf16(v0.z, h[2], l[2]); split_bf16(v0.w, h[3], l[3]);
    split_bf16(v1.x, h[4], l[4]); split_bf16(v1.y, h[5], l[5]);
    split_bf16(v1.z, h[6], l[6]); split_bf16(v1.w, h[7], l[7]);
    size_t o = (size_t)row * 1024 + k8;
    *(uint4*)(g_x2 + o)       = *(uint4*)h;
    *(uint4*)(g_x2 + o + 512) = *(uint4*)l;
}

__device__ __forceinline__ void conv_w_one(const float* __restrict__ W,
                                           __nv_bfloat16* __restrict__ Bh,
                                           __nv_bfloat16* __restrict__ Bl,
                                           int t, int K, int N, int Kpad) {
    int n = t / Kpad, k = t % Kpad;
    float w = (k < K) ? W[(size_t)k * N + n] : 0.f;
    __nv_bfloat16 hi, lo;
    split_bf16(w, hi, lo);
    Bh[t] = hi; Bl[t] = lo;
}
__global__ void conv_w_all_kernel(const float* __restrict__ W1,
                                  const float* __restrict__ W2,
                                  const float* __restrict__ W3) {
    int t = blockIdx.x * blockDim.x + threadIdx.x;
    if (t < 131072)        conv_w_one(W1, g_B1h, g_B1l, t,          IN_DIM, HID,    512);
    else if (t < 196608)   conv_w_one(W2, g_B2h, g_B2l, t - 131072, HID,    HID,    256);
    else if (t < 212992)   conv_w_one(W3, g_B3h, g_B3l, t - 196608, HID,    OUT_DIM, 256);
}

// ======================= HMMA split-bf16 GEMM (3-stage pipeline, BM=128) =======================
template <int BN, int K_SEG, int A_STRIDE, bool RELU, bool SPLIT_OUT, int N_FULL>
__global__ void __launch_bounds__(256, 2) mma_gemm_kernel(
    const __nv_bfloat16* __restrict__ A,
    const __nv_bfloat16* __restrict__ Bh,
    const __nv_bfloat16* __restrict__ Bl,
    const float* __restrict__ bias,
    void* __restrict__ outp)
{
    constexpr int BM = 128, BK = 64;
    constexpr int CPS = K_SEG / BK;
    constexpr int NCH = 3 * CPS;
    constexpr int A_BYTES = BM * 128;
    constexpr int B_BYTES = BN * 128;
    constexpr int STAGE = A_BYTES + B_BYTES;
    constexpr int WARP_N = BN / 2;
    constexpr int NB = WARP_N / 8;

    extern __shared__ char smem[];
    const uint32_t smem_b = smem_u32(smem);
    const int tid = threadIdx.x;
    const int wid = tid >> 5, lane = tid & 31;
    const int row0 = blockIdx.y * BM;
    const int col0 = blockIdx.x * BN;
    const int wm = (wid & 3) * 32;
    const int wn = (wid >> 2) * WARP_N;

    float acc[2][NB][4];
    #pragma unroll
    for (int mi = 0; mi < 2; mi++)
        #pragma unroll
        for (int ni = 0; ni < NB; ni++)
            #pragma unroll
            for (int q = 0; q < 4; q++) acc[mi][ni][q] = 0.f;

    auto issue_load = [&](int c, int buf) {
        int seg = c / CPS;
        int kk  = (c % CPS) * BK;
        const __nv_bfloat16* Asrc = A + (seg == 2 ? A_STRIDE / 2 : 0) + kk;
        const __nv_bfloat16* Bsrc = (seg == 1 ? Bl : Bh) + kk;
        uint32_t sa = smem_b + buf * STAGE;
        uint32_t sb = sa + A_BYTES;
        #pragma unroll
        for (int i = 0; i < 4; i++) {
            int idx = tid + i * 256;
            int r = idx >> 3, c8 = idx & 7;
            const void* g = Asrc + (size_t)(row0 + r) * A_STRIDE + c8 * 8;
            CP_ASYNC16(sa + (uint32_t)(r * 128 + ((c8 * 16) ^ ((r & 7) * 16))), g);
        }
        #pragma unroll
        for (int i = 0; i < BN / 32; i++) {
            int idx = tid + i * 256;
            int r = idx >> 3, c8 = idx & 7;
            const void* g = Bsrc + (size_t)(col0 + r) * K_SEG + c8 * 8;
            CP_ASYNC16(sb + (uint32_t)(r * 128 + ((c8 * 16) ^ ((r & 7) * 16))), g);
        }
        CP_COMMIT();
    };

    const int a_r7  = lane & 7;
    const int a_m8  = ((lane >> 3) & 1) * 8;
    const int a_cb  = ((lane >> 4) & 1) * 16;
    const int a_xor = a_r7 * 16;
    const int b_r7  = lane & 7;
    const int b_n8  = ((lane >> 4) & 1) * 8;
    const int b_cb  = ((lane >> 3) & 1) * 16;
    const int b_xor = b_r7 * 16;

    issue_load(0, 0);
    issue_load(1, 1);

    int buf = 0;
    for (int c = 0; c < NCH; c++) {
        CP_WAIT(1);
        __syncthreads();
        if (c + 2 < NCH) issue_load(c + 2, (c + 2) % 3);
        else             CP_COMMIT();

        const uint32_t sa = smem_b + buf * STAGE;
        const uint32_t sb = sa + A_BYTES;
        const uint32_t a_base0 = sa + (uint32_t)((wm + a_r7 + a_m8) * 128);
        const uint32_t a_base1 = a_base0 + 16 * 128;
        const uint32_t b_base  = sb + (uint32_t)((wn + b_r7 + b_n8) * 128);

        #pragma unroll
        for (int k16 = 0; k16 < 4; k16++) {
            const int kb = k16 * 32;
            uint32_t A0[4], A1[4];
            LDMATRIX_X4(A0[0], A0[1], A0[2], A0[3], a_base0 + ((kb + a_cb) ^ a_xor));
            LDMATRIX_X4(A1[0], A1[1], A1[2], A1[3], a_base1 + ((kb + a_cb) ^ a_xor));
            #pragma unroll
            for (int j = 0; j < NB / 2; j++) {
                uint32_t B4[4];
                LDMATRIX_X4(B4[0], B4[1], B4[2], B4[3],
                            b_base + (uint32_t)(j * 2048) + ((kb + b_cb) ^ b_xor));
                MMA_16816(acc[0][2 * j + 0], A0[0], A0[1], A0[2], A0[3], B4[0], B4[1]);
                MMA_16816(acc[0][2 * j + 1], A0[0], A0[1], A0[2], A0[3], B4[2], B4[3]);
                MMA_16816(acc[1][2 * j + 0], A1[0], A1[1], A1[2], A1[3], B4[0], B4[1]);
                MMA_16816(acc[1][2 * j + 1], A1[0], A1[1], A1[2], A1[3], B4[2], B4[3]);
            }
        }
        buf = (buf + 1 == 3) ? 0 : buf + 1;
    }

    const int qrow = lane >> 2;
    const int qcol = (lane & 3) * 2;
    #pragma unroll
    for (int mi = 0; mi < 2; mi++) {
        #pragma unroll
        for (int ni = 0; ni < NB; ni++) {
            const int col = col0 + wn + ni * 8 + qcol;
            const float bv0 = __ldg(bias + col);
            const float bv1 = __ldg(bias + col + 1);
            #pragma unroll
            for (int h = 0; h < 2; h++) {
                const int row = row0 + wm + mi * 16 + qrow + h * 8;
                float v0 = acc[mi][ni][h * 2 + 0] + bv0;
                float v1 = acc[mi][ni][h * 2 + 1] + bv1;
                if (RELU) { v0 = fmaxf(v0, 0.f); v1 = fmaxf(v1, 0.f); }
                if (SPLIT_OUT) {
                    __nv_bfloat16* outb = (__nv_bfloat16*)outp;
                    __nv_bfloat162 hi, lo;
                    split_bf16(v0, hi.x, lo.x);
                    split_bf16(v1, hi.y, lo.y);
                    size_t o = (size_t)row * (2 * N_FULL);
                    *(__nv_bfloat162*)(outb + o + col)          = hi;
                    *(__nv_bfloat162*)(outb + o + N_FULL + col) = lo;
                } else {
                    float* outf = (float*)outp;
                    float2 v = make_float2(v0, v1);
                    *(float2*)(outf + (size_t)row * N_FULL + col) = v;
                }
            }
        }
    }
}

// ======================= CSR build (side stream, even-padded degrees) =======================
__global__ void zero_counts_kernel() {
    int i = blockIdx.x * blockDim.x + threadIdx.x;
    if (i < N_NODES) { g_deg[i] = 0; g_cur[i] = 0; }
}
__global__ void count_deg_kernel(const int* __restrict__ erow) {
    int e = blockIdx.x * blockDim.x + threadIdx.x;
    if (e < E_EDGES) atomicAdd(&g_deg[erow[e]], 1);
}
__global__ void scan1_kernel() {      // scan over degrees padded to even
    __shared__ int wsums[32];
    const int tid = threadIdx.x;
    const int i = blockIdx.x * 1024 + tid;
    const int v = (g_deg[i] + 1) & ~1;
    int x = v;
    #pragma unroll
    for (int o = 1; o < 32; o <<= 1) {
        int t = __shfl_up_sync(0xFFFFFFFFu, x, o);
        if ((tid & 31) >= o) x += t;
    }
    if ((tid & 31) == 31) wsums[tid >> 5] = x;
    __syncthreads();
    if (tid < 32) {
        int y = wsums[tid];
        #pragma unroll
        for (int o = 1; o < 32; o <<= 1) {
            int t = __shfl_up_sync(0xFFFFFFFFu, y, o);
            if (tid >= o) y += t;
        }
        wsums[tid] = y;
    }
    __syncthreads();
    const int warp = tid >> 5;
    const int base = warp ? wsums[warp - 1] : 0;
    g_off[i] = base + x - v;
    if (tid == 1023) g_bsum[blockIdx.x] = wsums[31];
}
__global__ void scan2_kernel() {   // 1 block, 64 threads
    __shared__ int s0;
    const int tid = threadIdx.x;
    const int v = g_bsum[tid];
    int x = v;
    #pragma unroll
    for (int o = 1; o < 32; o <<= 1) {
        int t = __shfl_up_sync(0xFFFFFFFFu, x, o);
        if ((tid & 31) >= o) x += t;
    }
    if (tid == 31) s0 = x;
    __syncthreads();
    const int add = (tid >= 32) ? s0 : 0;
    g_boff[tid] = add + x - v;
}
__global__ void scan3_kernel() {   // 64 blocks x 1024
    const int i = blockIdx.x * 1024 + threadIdx.x;
    const int o = g_off[i] + g_boff[blockIdx.x];
    g_off[i] = o;
    if (i == N_NODES - 1) g_off[N_NODES] = o + ((g_deg[i] + 1) & ~1);
}
__global__ void pad_fill_kernel() {   // zero filler slot for odd-degree nodes
    const int i = blockIdx.x * blockDim.x + threadIdx.x;
    if (i < N_NODES) {
        const int d = g_deg[i];
        if (d & 1) g_edges[g_off[i] + d] = make_int2(0, 0);
    }
}
__global__ void fill_csr_kernel(const int* __restrict__ erow,
                                const int* __restrict__ ecol,
                                const float* __restrict__ ew) {
    int e = blockIdx.x * blockDim.x + threadIdx.x;
    if (e < E_EDGES) {
        int r = erow[e];
        int p = g_off[r] + atomicAdd(&g_cur[r], 1);
        g_edges[p] = make_int2(ecol[e], __float_as_int(0.9f * ew[e]));
    }
}

// ======================= propagation (one warp per node, paired edges) =======================
__global__ void prop_kernel(const float* __restrict__ src,
                            const float* __restrict__ h0,
                            float* __restrict__ dst) {
    const int gw   = (blockIdx.x * blockDim.x + threadIdx.x) >> 5;
    const int lane = threadIdx.x & 31;
    if (gw >= N_NODES) return;
    const int s = g_off[gw];        // even
    const int e = g_off[gw + 1];    // even
    const int half = lane >> 4;
    const int fq   = lane & 15;

    float4 a = make_float4(0.f, 0.f, 0.f, 0.f);
    for (int i = s; i < e; i += 2) {
        const int4 ep = __ldg((const int4*)(g_edges + i));   // 2 edges, 16B aligned
        const int   col = half ? ep.z : ep.x;
        const float w   = __int_as_float(half ? ep.w : ep.y);
        const float4 v  = __ldg((const float4*)(src + ((size_t)col << 6)) + fq);
        a.x = fmaf(w, v.x, a.x);
        a.y = fmaf(w, v.y, a.y);
        a.z = fmaf(w, v.z, a.z);
        a.w = fmaf(w, v.w, a.w);
    }
    a.x += __shfl_xor_sync(0xFFFFFFFFu, a.x, 16);
    a.y += __shfl_xor_sync(0xFFFFFFFFu, a.y, 16);
    a.z += __shfl_xor_sync(0xFFFFFFFFu, a.z, 16);
    a.w += __shfl_xor_sync(0xFFFFFFFFu, a.w, 16);
    if (lane < 16) {
        const float4 hv = __ldg((const float4*)(h0 + ((size_t)gw << 6)) + fq);
        float4 o;
        o.x = fmaf(ALPHA_C, hv.x, a.x);
        o.y = fmaf(ALPHA_C, hv.y, a.y);
        o.z = fmaf(ALPHA_C, hv.z, a.z);
        o.w = fmaf(ALPHA_C, hv.w, a.w);
        ((float4*)(dst + ((size_t)gw << 6)))[fq] = o;
    }
}

// ======================= launch =======================
extern "C" void kernel_launch(void* const* d_in, const int* in_sizes, int n_in,
                              void* d_out, int out_size) {
    const float* x  = (const float*)d_in[0];
    const float* W1 = (const float*)d_in[1];
    const float* b1 = (const float*)d_in[2];
    const float* W2 = (const float*)d_in[3];
    const float* b2 = (const float*)d_in[4];
    const float* W3 = (const float*)d_in[5];
    const float* b3 = (const float*)d_in[6];
    const float* ew = (const float*)d_in[7];
    const int*   er = (const int*)d_in[8];
    const int*   ec = (const int*)d_in[9];
    float* out = (float*)d_out;

    float *h0, *ha;
    __nv_bfloat16 *x2, *h1s, *h2s, *B1h, *B1l, *B2h, *B2l, *B3h, *B3l;
    cudaGetSymbolAddress((void**)&h0,  g_h0);
    cudaGetSymbolAddress((void**)&ha,  g_ha);
    cudaGetSymbolAddress((void**)&x2,  g_x2);
    cudaGetSymbolAddress((void**)&h1s, g_h1s);
    cudaGetSymbolAddress((void**)&h2s, g_h2s);
    cudaGetSymbolAddress((void**)&B1h, g_B1h);
    cudaGetSymbolAddress((void**)&B1l, g_B1l);
    cudaGetSymbolAddress((void**)&B2h, g_B2h);
    cudaGetSymbolAddress((void**)&B2l, g_B2l);
    cudaGetSymbolAddress((void**)&B3h, g_B3h);
    cudaGetSymbolAddress((void**)&B3l, g_B3l);

    constexpr int SMEM_BN128 = 3 * (128 * 128 + 128 * 128);  // 98304
    constexpr int SMEM_BN64  = 3 * (128 * 128 + 64 * 128);   // 73728

    static cudaStream_t s2;
    static cudaEvent_t evF, evJ;
    static bool inited = false;
    if (!inited) {
        cudaStreamCreateWithFlags(&s2, cudaStreamNonBlocking);
        cudaEventCreateWithFlags(&evF, cudaEventDisableTiming);
        cudaEventCreateWithFlags(&evJ, cudaEventDisableTiming);
        cudaFuncSetAttribute(mma_gemm_kernel<128, 512, 1024, true,  true,  256>,
                             cudaFuncAttributeMaxDynamicSharedMemorySize, SMEM_BN128);
        cudaFuncSetAttribute(mma_gemm_kernel<128, 256, 512,  true,  true,  256>,
                             cudaFuncAttributeMaxDynamicSharedMemorySize, SMEM_BN128);
        cudaFuncSetAttribute(mma_gemm_kernel<64,  256, 512,  false, false, 64>,
                             cudaFuncAttributeMaxDynamicSharedMemorySize, SMEM_BN64);
        inited = true;
    }

    // ---- fork: CSR chain on side stream, overlapped with conv + GEMMs ----
    cudaEventRecord(evF, 0);
    cudaStreamWaitEvent(s2, evF, 0);

    zero_counts_kernel<<<N_NODES / 256, 256, 0, s2>>>();
    count_deg_kernel<<<E_EDGES / 256, 256, 0, s2>>>(er);
    scan1_kernel<<<64, 1024, 0, s2>>>();
    scan2_kernel<<<1, 64, 0, s2>>>();
    scan3_kernel<<<64, 1024, 0, s2>>>();
    pad_fill_kernel<<<N_NODES / 256, 256, 0, s2>>>();
    fill_csr_kernel<<<E_EDGES / 256, 256, 0, s2>>>(er, ec, ew);
    cudaEventRecord(evJ, s2);

    // ---- main stream: conversions + MLP ----
    conv_x_kernel<<<(N_NODES * 64) / 256, 256>>>(x);
    conv_w_all_kernel<<<(212992 + 255) / 256, 256>>>(W1, W2, W3);

    mma_gemm_kernel<128, 512, 1024, true,  true,  256>
        <<<dim3(2, N_NODES / 128), 256, SMEM_BN128>>>(x2,  B1h, B1l, b1, h1s);
    mma_gemm_kernel<128, 256, 512,  true,  true,  256>
        <<<dim3(2, N_NODES / 128), 256, SMEM_BN128>>>(h1s, B2h, B2l, b2, h2s);
    mma_gemm_kernel<64,  256, 512,  false, false, 64>
        <<<dim3(1, N_NODES / 128), 256, SMEM_BN64>>>(h2s, B3h, B3l, b3, h0);

    // ---- join, then K=10 propagation steps (one warp per node) ----
    cudaStreamWaitEvent(0, evJ, 0);
    const float* src = h0;
    for (int s = 0; s < K_STEPS; s++) {
        float* dst = (s % 2 == 0) ? ha : out;
        prop_kernel<<<N_NODES / 8, 256>>>(src, h0, dst);
        src = dst;
    }
}

// round 10
// speedup vs baseline: 1.1612x; 1.0596x over previous
#include <cuda_runtime.h>
#include <cuda_bf16.h>
#include <cstdint>

#define N_NODES 65536
#define E_EDGES 1048576
#define IN_DIM  500
#define HID     256
#define OUT_DIM 64
#define ALPHA_C 0.1f
#define K_STEPS 10

// ======================= helpers =======================
__device__ __forceinline__ uint32_t smem_u32(const void* p) {
    uint32_t a;
    asm("{ .reg .u64 t; cvta.to.shared.u64 t, %1; cvt.u32.u64 %0, t; }" : "=r"(a) : "l"(p));
    return a;
}
#define CP_ASYNC16(dst, src) \
    asm volatile("cp.async.cg.shared.global [%0], [%1], 16;" :: "r"(dst), "l"(src) : "memory")
#define CP_COMMIT()  asm volatile("cp.async.commit_group;" ::: "memory")
#define CP_WAIT(n)   asm volatile("cp.async.wait_group %0;" :: "n"(n) : "memory")

#define LDMATRIX_X4(r0, r1, r2, r3, addr) \
    asm volatile("ldmatrix.sync.aligned.m8n8.x4.shared.b16 {%0,%1,%2,%3}, [%4];" \
        : "=r"(r0), "=r"(r1), "=r"(r2), "=r"(r3) : "r"(addr))

#define MMA_16816(d, a0, a1, a2, a3, b0, b1) \
    asm volatile("mma.sync.aligned.m16n8k16.row.col.f32.bf16.bf16.f32 " \
        "{%0,%1,%2,%3}, {%4,%5,%6,%7}, {%8,%9}, {%0,%1,%2,%3};" \
        : "+f"((d)[0]), "+f"((d)[1]), "+f"((d)[2]), "+f"((d)[3]) \
        : "r"(a0), "r"(a1), "r"(a2), "r"(a3), "r"(b0), "r"(b1))

// ======================= device scratch (no allocs) =======================
__device__ __align__(256) __nv_bfloat16 g_x2[(size_t)N_NODES * 1024];  // hi cols 0..511, lo 512..1023
__device__ __align__(256) __nv_bfloat16 g_h1s[(size_t)N_NODES * 512];  // hi 0..255, lo 256..511
__device__ __align__(256) __nv_bfloat16 g_h2s[(size_t)N_NODES * 512];
__device__ __align__(256) float g_h0[(size_t)N_NODES * OUT_DIM];
__device__ __align__(256) float g_ha[(size_t)N_NODES * OUT_DIM];
__device__ __align__(256) __nv_bfloat16 g_B1h[256 * 512], g_B1l[256 * 512];  // [N, Kpad]
__device__ __align__(256) __nv_bfloat16 g_B2h[256 * 256], g_B2l[256 * 256];
__device__ __align__(256) __nv_bfloat16 g_B3h[64 * 256],  g_B3l[64 * 256];
__device__ int   g_deg[N_NODES];
__device__ int   g_cur[N_NODES];
__device__ int   g_off[N_NODES + 1];
__device__ int   g_bsum[64];
__device__ int   g_boff[64];
__device__ __align__(16) int2 g_edges[E_EDGES];

// ======================= bf16 split conversion =======================
__device__ __forceinline__ void split_bf16(float v, __nv_bfloat16& hi, __nv_bfloat16& lo) {
    hi = __float2bfloat16_rn(v);
    lo = __float2bfloat16_rn(v - __bfloat162float(hi));
}

// x [65536, 500] f32 -> g_x2 [65536, 1024] split-bf16 (K padded to 512)
__global__ void conv_x_kernel(const float* __restrict__ x) {
    int t = blockIdx.x * blockDim.x + threadIdx.x;   // N_NODES*64 threads
    int row = t >> 6;
    int k8  = (t & 63) * 8;
    float4 v0 = make_float4(0.f, 0.f, 0.f, 0.f);
    float4 v1 = make_float4(0.f, 0.f, 0.f, 0.f);
    if (k8 + 3 < IN_DIM) v0 = *(const float4*)(x + (size_t)row * IN_DIM + k8);
    if (k8 + 7 < IN_DIM) v1 = *(const float4*)(x + (size_t)row * IN_DIM + k8 + 4);
    __align__(16) __nv_bfloat16 h[8], l[8];
    split_bf16(v0.x, h[0], l[0]); split_bf16(v0.y, h[1], l[1]);
    split_bf16(v0.z, h[2], l[2]); split_bf16(v0.w, h[3], l[3]);
    split_bf16(v1.x, h[4], l[4]); split_bf16(v1.y, h[5], l[5]);
    split_bf16(v1.z, h[6], l[6]); split_bf16(v1.w, h[7], l[7]);
    size_t o = (size_t)row * 1024 + k8;
    *(uint4*)(g_x2 + o)       = *(uint4*)h;
    *(uint4*)(g_x2 + o + 512) = *(uint4*)l;
}

__device__ __forceinline__ void conv_w_one(const float* __restrict__ W,
                                           __nv_bfloat16* __restrict__ Bh,
                                           __nv_bfloat16* __restrict__ Bl,
                                           int t, int K, int N, int Kpad) {
    int n = t / Kpad, k = t % Kpad;
    float w = (k < K) ? W[(size_t)k * N + n] : 0.f;
    __nv_bfloat16 hi, lo;
    split_bf16(w, hi, lo);
    Bh[t] = hi; Bl[t] = lo;
}
__global__ void conv_w_all_kernel(const float* __restrict__ W1,
                                  const float* __restrict__ W2,
                                  const float* __restrict__ W3) {
    int t = blockIdx.x * blockDim.x + threadIdx.x;
    if (t < 131072)        conv_w_one(W1, g_B1h, g_B1l, t,          IN_DIM, HID,    512);
    else if (t < 196608)   conv_w_one(W2, g_B2h, g_B2l, t - 131072, HID,    HID,    256);
    else if (t < 212992)   conv_w_one(W3, g_B3h, g_B3l, t - 196608, HID,    OUT_DIM, 256);
}

// ======================= HMMA split-bf16 GEMM (A-reuse, 2-phase) =======================
// D = Ahi*(Bh+Bl) + Alo*Bh. Phase 1 (c < CPS): load Ahi_k once + Bh_k + Bl_k, 2 MMA sets.
// Phase 2 (c >= CPS): Alo_k * Bh_k. A-operand traffic cut 33% vs 3-segment form.
template <int BN, int K_SEG, int A_STRIDE, bool RELU, bool SPLIT_OUT, int N_FULL>
__global__ void __launch_bounds__(256, 2) mma_gemm_kernel(
    const __nv_bfloat16* __restrict__ A,
    const __nv_bfloat16* __restrict__ Bh,
    const __nv_bfloat16* __restrict__ Bl,
    const float* __restrict__ bias,
    void* __restrict__ outp)
{
    constexpr int BM = 128, BK = 64;
    constexpr int CPS = K_SEG / BK;
    constexpr int NCH = 2 * CPS;
    constexpr int A_BYTES = BM * 128;
    constexpr int B_BYTES = BN * 128;
    constexpr int STAGE = A_BYTES + 2 * B_BYTES;
    constexpr int WARP_N = BN / 2;
    constexpr int NB = WARP_N / 8;

    extern __shared__ char smem[];
    const uint32_t smem_b = smem_u32(smem);
    const int tid = threadIdx.x;
    const int wid = tid >> 5, lane = tid & 31;
    const int row0 = blockIdx.y * BM;
    const int col0 = blockIdx.x * BN;
    const int wm = (wid & 3) * 32;
    const int wn = (wid >> 2) * WARP_N;

    float acc[2][NB][4];
    #pragma unroll
    for (int mi = 0; mi < 2; mi++)
        #pragma unroll
        for (int ni = 0; ni < NB; ni++)
            #pragma unroll
            for (int q = 0; q < 4; q++) acc[mi][ni][q] = 0.f;

    auto issue_load = [&](int c, int buf) {
        const bool ph1 = (c < CPS);
        const int kk = (ph1 ? c : c - CPS) * BK;
        const __nv_bfloat16* Asrc = A + (ph1 ? 0 : A_STRIDE / 2) + kk;
        uint32_t sa  = smem_b + buf * STAGE;
        uint32_t sb0 = sa + A_BYTES;
        uint32_t sb1 = sb0 + B_BYTES;
        #pragma unroll
        for (int i = 0; i < 4; i++) {
            int idx = tid + i * 256;
            int r = idx >> 3, c8 = idx & 7;
            const void* g = Asrc + (size_t)(row0 + r) * A_STRIDE + c8 * 8;
            CP_ASYNC16(sa + (uint32_t)(r * 128 + ((c8 * 16) ^ ((r & 7) * 16))), g);
        }
        #pragma unroll
        for (int i = 0; i < BN / 32; i++) {
            int idx = tid + i * 256;
            int r = idx >> 3, c8 = idx & 7;
            uint32_t so = (uint32_t)(r * 128 + ((c8 * 16) ^ ((r & 7) * 16)));
            const void* gh = Bh + (size_t)(col0 + r) * K_SEG + kk + c8 * 8;
            CP_ASYNC16(sb0 + so, gh);
            if (ph1) {
                const void* gl = Bl + (size_t)(col0 + r) * K_SEG + kk + c8 * 8;
                CP_ASYNC16(sb1 + so, gl);
            }
        }
        CP_COMMIT();
    };

    const int a_r7  = lane & 7;
    const int a_m8  = ((lane >> 3) & 1) * 8;
    const int a_cb  = ((lane >> 4) & 1) * 16;
    const int a_xor = a_r7 * 16;
    const int b_r7  = lane & 7;
    const int b_n8  = ((lane >> 4) & 1) * 8;
    const int b_cb  = ((lane >> 3) & 1) * 16;
    const int b_xor = b_r7 * 16;

    issue_load(0, 0);

    for (int c = 0; c < NCH; c++) {
        if (c + 1 < NCH) { issue_load(c + 1, (c + 1) & 1); CP_WAIT(1); }
        else             { CP_WAIT(0); }
        __syncthreads();

        const bool ph1 = (c < CPS);
        const uint32_t sa  = smem_b + (c & 1) * STAGE;
        const uint32_t sb0 = sa + A_BYTES;
        const uint32_t sb1 = sb0 + B_BYTES;
        const uint32_t a_base0 = sa + (uint32_t)((wm + a_r7 + a_m8) * 128);
        const uint32_t a_base1 = a_base0 + 16 * 128;
        const uint32_t b_off   = (uint32_t)((wn + b_r7 + b_n8) * 128);

        #pragma unroll
        for (int k16 = 0; k16 < 4; k16++) {
            const int kb = k16 * 32;
            uint32_t A0[4], A1[4];
            LDMATRIX_X4(A0[0], A0[1], A0[2], A0[3], a_base0 + ((kb + a_cb) ^ a_xor));
            LDMATRIX_X4(A1[0], A1[1], A1[2], A1[3], a_base1 + ((kb + a_cb) ^ a_xor));
            #pragma unroll
            for (int j = 0; j < NB / 2; j++) {
                uint32_t B4[4];
                LDMATRIX_X4(B4[0], B4[1], B4[2], B4[3],
                            sb0 + b_off + (uint32_t)(j * 2048) + ((kb + b_cb) ^ b_xor));
                MMA_16816(acc[0][2 * j + 0], A0[0], A0[1], A0[2], A0[3], B4[0], B4[1]);
                MMA_16816(acc[0][2 * j + 1], A0[0], A0[1], A0[2], A0[3], B4[2], B4[3]);
                MMA_16816(acc[1][2 * j + 0], A1[0], A1[1], A1[2], A1[3], B4[0], B4[1]);
                MMA_16816(acc[1][2 * j + 1], A1[0], A1[1], A1[2], A1[3], B4[2], B4[3]);
            }
            if (ph1) {
                #pragma unroll
                for (int j = 0; j < NB / 2; j++) {
                    uint32_t B4[4];
                    LDMATRIX_X4(B4[0], B4[1], B4[2], B4[3],
                                sb1 + b_off + (uint32_t)(j * 2048) + ((kb + b_cb) ^ b_xor));
                    MMA_16816(acc[0][2 * j + 0], A0[0], A0[1], A0[2], A0[3], B4[0], B4[1]);
                    MMA_16816(acc[0][2 * j + 1], A0[0], A0[1], A0[2], A0[3], B4[2], B4[3]);
                    MMA_16816(acc[1][2 * j + 0], A1[0], A1[1], A1[2], A1[3], B4[0], B4[1]);
                    MMA_16816(acc[1][2 * j + 1], A1[0], A1[1], A1[2], A1[3], B4[2], B4[3]);
                }
            }
        }
        __syncthreads();
    }

    const int qrow = lane >> 2;
    const int qcol = (lane & 3) * 2;
    #pragma unroll
    for (int mi = 0; mi < 2; mi++) {
        #pragma unroll
        for (int ni = 0; ni < NB; ni++) {
            const int col = col0 + wn + ni * 8 + qcol;
            const float bv0 = __ldg(bias + col);
            const float bv1 = __ldg(bias + col + 1);
            #pragma unroll
            for (int h = 0; h < 2; h++) {
                const int row = row0 + wm + mi * 16 + qrow + h * 8;
                float v0 = acc[mi][ni][h * 2 + 0] + bv0;
                float v1 = acc[mi][ni][h * 2 + 1] + bv1;
                if (RELU) { v0 = fmaxf(v0, 0.f); v1 = fmaxf(v1, 0.f); }
                if (SPLIT_OUT) {
                    __nv_bfloat16* outb = (__nv_bfloat16*)outp;
                    __nv_bfloat162 hi, lo;
                    split_bf16(v0, hi.x, lo.x);
                    split_bf16(v1, hi.y, lo.y);
                    size_t o = (size_t)row * (2 * N_FULL);
                    *(__nv_bfloat162*)(outb + o + col)          = hi;
                    *(__nv_bfloat162*)(outb + o + N_FULL + col) = lo;
                } else {
                    float* outf = (float*)outp;
                    float2 v = make_float2(v0, v1);
                    *(float2*)(outf + (size_t)row * N_FULL + col) = v;
                }
            }
        }
    }
}

// ======================= CSR build (side stream) =======================
__global__ void zero_counts_kernel() {
    int i = blockIdx.x * blockDim.x + threadIdx.x;
    if (i < N_NODES) { g_deg[i] = 0; g_cur[i] = 0; }
}
__global__ void count_deg_kernel(const int* __restrict__ erow) {
    int e = blockIdx.x * blockDim.x + threadIdx.x;
    if (e < E_EDGES) atomicAdd(&g_deg[erow[e]], 1);
}
__global__ void scan1_kernel() {
    __shared__ int wsums[32];
    const int tid = threadIdx.x;
    const int i = blockIdx.x * 1024 + tid;
    const int v = g_deg[i];
    int x = v;
    #pragma unroll
    for (int o = 1; o < 32; o <<= 1) {
        int t = __shfl_up_sync(0xFFFFFFFFu, x, o);
        if ((tid & 31) >= o) x += t;
    }
    if ((tid & 31) == 31) wsums[tid >> 5] = x;
    __syncthreads();
    if (tid < 32) {
        int y = wsums[tid];
        #pragma unroll
        for (int o = 1; o < 32; o <<= 1) {
            int t = __shfl_up_sync(0xFFFFFFFFu, y, o);
            if (tid >= o) y += t;
        }
        wsums[tid] = y;
    }
    __syncthreads();
    const int warp = tid >> 5;
    const int base = warp ? wsums[warp - 1] : 0;
    g_off[i] = base + x - v;
    if (tid == 1023) g_bsum[blockIdx.x] = wsums[31];
}
__global__ void scan2_kernel() {   // 1 block, 64 threads
    __shared__ int s0;
    const int tid = threadIdx.x;
    const int v = g_bsum[tid];
    int x = v;
    #pragma unroll
    for (int o = 1; o < 32; o <<= 1) {
        int t = __shfl_up_sync(0xFFFFFFFFu, x, o);
        if ((tid & 31) >= o) x += t;
    }
    if (tid == 31) s0 = x;
    __syncthreads();
    const int add = (tid >= 32) ? s0 : 0;
    g_boff[tid] = add + x - v;
}
__global__ void scan3_kernel() {   // 64 blocks x 1024
    const int i = blockIdx.x * 1024 + threadIdx.x;
    g_off[i] += g_boff[blockIdx.x];
    if (i == 0) g_off[N_NODES] = E_EDGES;
}
__global__ void fill_csr_kernel(const int* __restrict__ erow,
                                const int* __restrict__ ecol,
                                const float* __restrict__ ew) {
    int e = blockIdx.x * blockDim.x + threadIdx.x;
    if (e < E_EDGES) {
        int r = erow[e];
        int p = g_off[r] + atomicAdd(&g_cur[r], 1);
        g_edges[p] = make_int2(ecol[e], __float_as_int(0.9f * ew[e]));
    }
}

// ======================= propagation (one warp per node) =======================
__global__ void prop_kernel(const float* __restrict__ src,
                            const float* __restrict__ h0,
                            float* __restrict__ dst) {
    const int gw   = (blockIdx.x * blockDim.x + threadIdx.x) >> 5;
    const int lane = threadIdx.x & 31;
    if (gw >= N_NODES) return;
    const int s = g_off[gw];
    const int e = g_off[gw + 1];
    const int half = lane >> 4;
    const int fq   = lane & 15;

    float4 a = make_float4(0.f, 0.f, 0.f, 0.f);
    for (int i = s; i < e; i += 2) {
        const int2 e0 = __ldg(&g_edges[i]);
        int2 e1;
        if (i + 1 < e) e1 = __ldg(&g_edges[i + 1]);
        else           e1 = make_int2(e0.x, 0);
        const int   col = half ? e1.x : e0.x;
        const float w   = __int_as_float(half ? e1.y : e0.y);
        const float4 v  = __ldg((const float4*)(src + ((size_t)col << 6)) + fq);
        a.x = fmaf(w, v.x, a.x);
        a.y = fmaf(w, v.y, a.y);
        a.z = fmaf(w, v.z, a.z);
        a.w = fmaf(w, v.w, a.w);
    }
    a.x += __shfl_xor_sync(0xFFFFFFFFu, a.x, 16);
    a.y += __shfl_xor_sync(0xFFFFFFFFu, a.y, 16);
    a.z += __shfl_xor_sync(0xFFFFFFFFu, a.z, 16);
    a.w += __shfl_xor_sync(0xFFFFFFFFu, a.w, 16);
    if (lane < 16) {
        const float4 hv = __ldg((const float4*)(h0 + ((size_t)gw << 6)) + fq);
        float4 o;
        o.x = fmaf(ALPHA_C, hv.x, a.x);
        o.y = fmaf(ALPHA_C, hv.y, a.y);
        o.z = fmaf(ALPHA_C, hv.z, a.z);
        o.w = fmaf(ALPHA_C, hv.w, a.w);
        ((float4*)(dst + ((size_t)gw << 6)))[fq] = o;
    }
}

// ======================= launch =======================
extern "C" void kernel_launch(void* const* d_in, const int* in_sizes, int n_in,
                              void* d_out, int out_size) {
    const float* x  = (const float*)d_in[0];
    const float* W1 = (const float*)d_in[1];
    const float* b1 = (const float*)d_in[2];
    const float* W2 = (const float*)d_in[3];
    const float* b2 = (const float*)d_in[4];
    const float* W3 = (const float*)d_in[5];
    const float* b3 = (const float*)d_in[6];
    const float* ew = (const float*)d_in[7];
    const int*   er = (const int*)d_in[8];
    const int*   ec = (const int*)d_in[9];
    float* out = (float*)d_out;

    float *h0, *ha;
    __nv_bfloat16 *x2, *h1s, *h2s, *B1h, *B1l, *B2h, *B2l, *B3h, *B3l;
    cudaGetSymbolAddress((void**)&h0,  g_h0);
    cudaGetSymbolAddress((void**)&ha,  g_ha);
    cudaGetSymbolAddress((void**)&x2,  g_x2);
    cudaGetSymbolAddress((void**)&h1s, g_h1s);
    cudaGetSymbolAddress((void**)&h2s, g_h2s);
    cudaGetSymbolAddress((void**)&B1h, g_B1h);
    cudaGetSymbolAddress((void**)&B1l, g_B1l);
    cudaGetSymbolAddress((void**)&B2h, g_B2h);
    cudaGetSymbolAddress((void**)&B2l, g_B2l);
    cudaGetSymbolAddress((void**)&B3h, g_B3h);
    cudaGetSymbolAddress((void**)&B3l, g_B3l);

    constexpr int SMEM_BN128 = 2 * (128 * 128 + 2 * 128 * 128);  // 98304
    constexpr int SMEM_BN64  = 2 * (128 * 128 + 2 * 64 * 128);   // 65536

    static cudaStream_t s2;
    static cudaEvent_t evF, evJ;
    static bool inited = false;
    if (!inited) {
        cudaStreamCreateWithFlags(&s2, cudaStreamNonBlocking);
        cudaEventCreateWithFlags(&evF, cudaEventDisableTiming);
        cudaEventCreateWithFlags(&evJ, cudaEventDisableTiming);
        cudaFuncSetAttribute(mma_gemm_kernel<128, 512, 1024, true,  true,  256>,
                             cudaFuncAttributeMaxDynamicSharedMemorySize, SMEM_BN128);
        cudaFuncSetAttribute(mma_gemm_kernel<128, 256, 512,  true,  true,  256>,
                             cudaFuncAttributeMaxDynamicSharedMemorySize, SMEM_BN128);
        cudaFuncSetAttribute(mma_gemm_kernel<64,  256, 512,  false, false, 64>,
                             cudaFuncAttributeMaxDynamicSharedMemorySize, SMEM_BN64);
        inited = true;
    }

    // ---- fork: CSR chain on side stream, overlapped with conv + GEMMs ----
    cudaEventRecord(evF, 0);
    cudaStreamWaitEvent(s2, evF, 0);

    zero_counts_kernel<<<N_NODES / 256, 256, 0, s2>>>();
    count_deg_kernel<<<E_EDGES / 256, 256, 0, s2>>>(er);
    scan1_kernel<<<64, 1024, 0, s2>>>();
    scan2_kernel<<<1, 64, 0, s2>>>();
    scan3_kernel<<<64, 1024, 0, s2>>>();
    fill_csr_kernel<<<E_EDGES / 256, 256, 0, s2>>>(er, ec, ew);
    cudaEventRecord(evJ, s2);

    // ---- main stream: conversions + MLP ----
    conv_x_kernel<<<(N_NODES * 64) / 256, 256>>>(x);
    conv_w_all_kernel<<<(212992 + 255) / 256, 256>>>(W1, W2, W3);

    mma_gemm_kernel<128, 512, 1024, true,  true,  256>
        <<<dim3(2, N_NODES / 128), 256, SMEM_BN128>>>(x2,  B1h, B1l, b1, h1s);
    mma_gemm_kernel<128, 256, 512,  true,  true,  256>
        <<<dim3(2, N_NODES / 128), 256, SMEM_BN128>>>(h1s, B2h, B2l, b2, h2s);
    mma_gemm_kernel<64,  256, 512,  false, false, 64>
        <<<dim3(1, N_NODES / 128), 256, SMEM_BN64>>>(h2s, B3h, B3l, b3, h0);

    // ---- join, then K=10 propagation steps (one warp per node) ----
    cudaStreamWaitEvent(0, evJ, 0);
    const float* src = h0;
    for (int s = 0; s < K_STEPS; s++) {
        float* dst = (s % 2 == 0) ? ha : out;
        prop_kernel<<<N_NODES / 8, 256>>>(src, h0, dst);
        src = dst;
    }
}

// round 11
// speedup vs baseline: 1.1657x; 1.0039x over previous
#include <cuda_runtime.h>
#include <cuda_bf16.h>
#include <cstdint>

#define N_NODES 65536
#define E_EDGES 1048576
#define IN_DIM  500
#define HID     256
#define OUT_DIM 64
#define ALPHA_C 0.1f
#define K_STEPS 10

// ======================= helpers =======================
__device__ __forceinline__ uint32_t smem_u32(const void* p) {
    uint32_t a;
    asm("{ .reg .u64 t; cvta.to.shared.u64 t, %1; cvt.u32.u64 %0, t; }" : "=r"(a) : "l"(p));
    return a;
}
#define CP_ASYNC16(dst, src) \
    asm volatile("cp.async.cg.shared.global [%0], [%1], 16;" :: "r"(dst), "l"(src) : "memory")
#define CP_COMMIT()  asm volatile("cp.async.commit_group;" ::: "memory")
#define CP_WAIT(n)   asm volatile("cp.async.wait_group %0;" :: "n"(n) : "memory")

#define LDMATRIX_X4(r0, r1, r2, r3, addr) \
    asm volatile("ldmatrix.sync.aligned.m8n8.x4.shared.b16 {%0,%1,%2,%3}, [%4];" \
        : "=r"(r0), "=r"(r1), "=r"(r2), "=r"(r3) : "r"(addr))

#define MMA_16816(d, a0, a1, a2, a3, b0, b1) \
    asm volatile("mma.sync.aligned.m16n8k16.row.col.f32.bf16.bf16.f32 " \
        "{%0,%1,%2,%3}, {%4,%5,%6,%7}, {%8,%9}, {%0,%1,%2,%3};" \
        : "+f"((d)[0]), "+f"((d)[1]), "+f"((d)[2]), "+f"((d)[3]) \
        : "r"(a0), "r"(a1), "r"(a2), "r"(a3), "r"(b0), "r"(b1))

// ======================= device scratch (no allocs) =======================
__device__ __align__(256) __nv_bfloat16 g_x2[(size_t)N_NODES * 1024];  // hi cols 0..511, lo 512..1023
__device__ __align__(256) __nv_bfloat16 g_h1s[(size_t)N_NODES * 512];  // hi 0..255, lo 256..511
__device__ __align__(256) __nv_bfloat16 g_h2s[(size_t)N_NODES * 512];
__device__ __align__(256) float g_h0[(size_t)N_NODES * OUT_DIM];
__device__ __align__(256) float g_ha[(size_t)N_NODES * OUT_DIM];
__device__ __align__(256) __nv_bfloat16 g_B1h[256 * 512], g_B1l[256 * 512];  // [N, Kpad]
__device__ __align__(256) __nv_bfloat16 g_B2h[256 * 256], g_B2l[256 * 256];
__device__ __align__(256) __nv_bfloat16 g_B3h[64 * 256],  g_B3l[64 * 256];
__device__ int   g_deg[N_NODES];
__device__ int   g_cur[N_NODES];
__device__ int   g_off[N_NODES + 1];
__device__ int   g_bsum[64];
__device__ int   g_boff[64];
__device__ __align__(16) int2 g_edges[E_EDGES];

// ======================= bf16 split conversion =======================
__device__ __forceinline__ void split_bf16(float v, __nv_bfloat16& hi, __nv_bfloat16& lo) {
    hi = __float2bfloat16_rn(v);
    lo = __float2bfloat16_rn(v - __bfloat162float(hi));
}

// x [65536, 500] f32 -> g_x2 [65536, 1024] split-bf16 (K padded to 512)
__global__ void conv_x_kernel(const float* __restrict__ x) {
    int t = blockIdx.x * blockDim.x + threadIdx.x;   // N_NODES*64 threads
    int row = t >> 6;
    int k8  = (t & 63) * 8;
    float4 v0 = make_float4(0.f, 0.f, 0.f, 0.f);
    float4 v1 = make_float4(0.f, 0.f, 0.f, 0.f);
    if (k8 + 3 < IN_DIM) v0 = *(const float4*)(x + (size_t)row * IN_DIM + k8);
    if (k8 + 7 < IN_DIM) v1 = *(const float4*)(x + (size_t)row * IN_DIM + k8 + 4);
    __align__(16) __nv_bfloat16 h[8], l[8];
    split_bf16(v0.x, h[0], l[0]); split_bf16(v0.y, h[1], l[1]);
    split_bf16(v0.z, h[2], l[2]); split_bf16(v0.w, h[3], l[3]);
    split_bf16(v1.x, h[4], l[4]); split_bf16(v1.y, h[5], l[5]);
    split_bf16(v1.z, h[6], l[6]); split_bf16(v1.w, h[7], l[7]);
    size_t o = (size_t)row * 1024 + k8;
    *(uint4*)(g_x2 + o)       = *(uint4*)h;
    *(uint4*)(g_x2 + o + 512) = *(uint4*)l;
}

__device__ __forceinline__ void conv_w_one(const float* __restrict__ W,
                                           __nv_bfloat16* __restrict__ Bh,
                                           __nv_bfloat16* __restrict__ Bl,
                                           int t, int K, int N, int Kpad) {
    int n = t / Kpad, k = t % Kpad;
    float w = (k < K) ? W[(size_t)k * N + n] : 0.f;
    __nv_bfloat16 hi, lo;
    split_bf16(w, hi, lo);
    Bh[t] = hi; Bl[t] = lo;
}
__global__ void conv_w_all_kernel(const float* __restrict__ W1,
                                  const float* __restrict__ W2,
                                  const float* __restrict__ W3) {
    int t = blockIdx.x * blockDim.x + threadIdx.x;
    if (t < 131072)        conv_w_one(W1, g_B1h, g_B1l, t,          IN_DIM, HID,    512);
    else if (t < 196608)   conv_w_one(W2, g_B2h, g_B2l, t - 131072, HID,    HID,    256);
    else if (t < 212992)   conv_w_one(W3, g_B3h, g_B3l, t - 196608, HID,    OUT_DIM, 256);
}

// ======================= HMMA split-bf16 GEMM (A-reuse, 2-phase) =======================
// D = Ahi*(Bh+Bl) + Alo*Bh. Phase 1 (c < CPS): load Ahi_k once + Bh_k + Bl_k, 2 MMA sets.
// Phase 2 (c >= CPS): Alo_k * Bh_k. A-operand traffic cut 33% vs 3-segment form.
template <int BN, int K_SEG, int A_STRIDE, bool RELU, bool SPLIT_OUT, int N_FULL>
__global__ void __launch_bounds__(256, 2) mma_gemm_kernel(
    const __nv_bfloat16* __restrict__ A,
    const __nv_bfloat16* __restrict__ Bh,
    const __nv_bfloat16* __restrict__ Bl,
    const float* __restrict__ bias,
    void* __restrict__ outp)
{
    constexpr int BM = 128, BK = 64;
    constexpr int CPS = K_SEG / BK;
    constexpr int NCH = 2 * CPS;
    constexpr int A_BYTES = BM * 128;
    constexpr int B_BYTES = BN * 128;
    constexpr int STAGE = A_BYTES + 2 * B_BYTES;
    constexpr int WARP_N = BN / 2;
    constexpr int NB = WARP_N / 8;

    extern __shared__ char smem[];
    const uint32_t smem_b = smem_u32(smem);
    const int tid = threadIdx.x;
    const int wid = tid >> 5, lane = tid & 31;
    const int row0 = blockIdx.y * BM;
    const int col0 = blockIdx.x * BN;
    const int wm = (wid & 3) * 32;
    const int wn = (wid >> 2) * WARP_N;

    float acc[2][NB][4];
    #pragma unroll
    for (int mi = 0; mi < 2; mi++)
        #pragma unroll
        for (int ni = 0; ni < NB; ni++)
            #pragma unroll
            for (int q = 0; q < 4; q++) acc[mi][ni][q] = 0.f;

    auto issue_load = [&](int c, int buf) {
        const bool ph1 = (c < CPS);
        const int kk = (ph1 ? c : c - CPS) * BK;
        const __nv_bfloat16* Asrc = A + (ph1 ? 0 : A_STRIDE / 2) + kk;
        uint32_t sa  = smem_b + buf * STAGE;
        uint32_t sb0 = sa + A_BYTES;
        uint32_t sb1 = sb0 + B_BYTES;
        #pragma unroll
        for (int i = 0; i < 4; i++) {
            int idx = tid + i * 256;
            int r = idx >> 3, c8 = idx & 7;
            const void* g = Asrc + (size_t)(row0 + r) * A_STRIDE + c8 * 8;
            CP_ASYNC16(sa + (uint32_t)(r * 128 + ((c8 * 16) ^ ((r & 7) * 16))), g);
        }
        #pragma unroll
        for (int i = 0; i < BN / 32; i++) {
            int idx = tid + i * 256;
            int r = idx >> 3, c8 = idx & 7;
            uint32_t so = (uint32_t)(r * 128 + ((c8 * 16) ^ ((r & 7) * 16)));
            const void* gh = Bh + (size_t)(col0 + r) * K_SEG + kk + c8 * 8;
            CP_ASYNC16(sb0 + so, gh);
            if (ph1) {
                const void* gl = Bl + (size_t)(col0 + r) * K_SEG + kk + c8 * 8;
                CP_ASYNC16(sb1 + so, gl);
            }
        }
        CP_COMMIT();
    };

    const int a_r7  = lane & 7;
    const int a_m8  = ((lane >> 3) & 1) * 8;
    const int a_cb  = ((lane >> 4) & 1) * 16;
    const int a_xor = a_r7 * 16;
    const int b_r7  = lane & 7;
    const int b_n8  = ((lane >> 4) & 1) * 8;
    const int b_cb  = ((lane >> 3) & 1) * 16;
    const int b_xor = b_r7 * 16;

    issue_load(0, 0);

    for (int c = 0; c < NCH; c++) {
        if (c + 1 < NCH) { issue_load(c + 1, (c + 1) & 1); CP_WAIT(1); }
        else             { CP_WAIT(0); }
        __syncthreads();

        const bool ph1 = (c < CPS);
        const uint32_t sa  = smem_b + (c & 1) * STAGE;
        const uint32_t sb0 = sa + A_BYTES;
        const uint32_t sb1 = sb0 + B_BYTES;
        const uint32_t a_base0 = sa + (uint32_t)((wm + a_r7 + a_m8) * 128);
        const uint32_t a_base1 = a_base0 + 16 * 128;
        const uint32_t b_off   = (uint32_t)((wn + b_r7 + b_n8) * 128);

        #pragma unroll
        for (int k16 = 0; k16 < 4; k16++) {
            const int kb = k16 * 32;
            uint32_t A0[4], A1[4];
            LDMATRIX_X4(A0[0], A0[1], A0[2], A0[3], a_base0 + ((kb + a_cb) ^ a_xor));
            LDMATRIX_X4(A1[0], A1[1], A1[2], A1[3], a_base1 + ((kb + a_cb) ^ a_xor));
            #pragma unroll
            for (int j = 0; j < NB / 2; j++) {
                uint32_t B4[4];
                LDMATRIX_X4(B4[0], B4[1], B4[2], B4[3],
                            sb0 + b_off + (uint32_t)(j * 2048) + ((kb + b_cb) ^ b_xor));
                MMA_16816(acc[0][2 * j + 0], A0[0], A0[1], A0[2], A0[3], B4[0], B4[1]);
                MMA_16816(acc[0][2 * j + 1], A0[0], A0[1], A0[2], A0[3], B4[2], B4[3]);
                MMA_16816(acc[1][2 * j + 0], A1[0], A1[1], A1[2], A1[3], B4[0], B4[1]);
                MMA_16816(acc[1][2 * j + 1], A1[0], A1[1], A1[2], A1[3], B4[2], B4[3]);
            }
            if (ph1) {
                #pragma unroll
                for (int j = 0; j < NB / 2; j++) {
                    uint32_t B4[4];
                    LDMATRIX_X4(B4[0], B4[1], B4[2], B4[3],
                                sb1 + b_off + (uint32_t)(j * 2048) + ((kb + b_cb) ^ b_xor));
                    MMA_16816(acc[0][2 * j + 0], A0[0], A0[1], A0[2], A0[3], B4[0], B4[1]);
                    MMA_16816(acc[0][2 * j + 1], A0[0], A0[1], A0[2], A0[3], B4[2], B4[3]);
                    MMA_16816(acc[1][2 * j + 0], A1[0], A1[1], A1[2], A1[3], B4[0], B4[1]);
                    MMA_16816(acc[1][2 * j + 1], A1[0], A1[1], A1[2], A1[3], B4[2], B4[3]);
                }
            }
        }
        __syncthreads();
    }

    const int qrow = lane >> 2;
    const int qcol = (lane & 3) * 2;
    #pragma unroll
    for (int mi = 0; mi < 2; mi++) {
        #pragma unroll
        for (int ni = 0; ni < NB; ni++) {
            const int col = col0 + wn + ni * 8 + qcol;
            const float bv0 = __ldg(bias + col);
            const float bv1 = __ldg(bias + col + 1);
            #pragma unroll
            for (int h = 0; h < 2; h++) {
                const int row = row0 + wm + mi * 16 + qrow + h * 8;
                float v0 = acc[mi][ni][h * 2 + 0] + bv0;
                float v1 = acc[mi][ni][h * 2 + 1] + bv1;
                if (RELU) { v0 = fmaxf(v0, 0.f); v1 = fmaxf(v1, 0.f); }
                if (SPLIT_OUT) {
                    __nv_bfloat16* outb = (__nv_bfloat16*)outp;
                    __nv_bfloat162 hi, lo;
                    split_bf16(v0, hi.x, lo.x);
                    split_bf16(v1, hi.y, lo.y);
                    size_t o = (size_t)row * (2 * N_FULL);
                    *(__nv_bfloat162*)(outb + o + col)          = hi;
                    *(__nv_bfloat162*)(outb + o + N_FULL + col) = lo;
                } else {
                    float* outf = (float*)outp;
                    float2 v = make_float2(v0, v1);
                    *(float2*)(outf + (size_t)row * N_FULL + col) = v;
                }
            }
        }
    }
}

// ======================= CSR build (side stream) =======================
__global__ void zero_counts_kernel() {
    int i = blockIdx.x * blockDim.x + threadIdx.x;
    if (i < N_NODES) { g_deg[i] = 0; g_cur[i] = 0; }
}
__global__ void count_deg_kernel(const int* __restrict__ erow) {
    int e = blockIdx.x * blockDim.x + threadIdx.x;
    if (e < E_EDGES) atomicAdd(&g_deg[erow[e]], 1);
}
__global__ void scan1_kernel() {
    __shared__ int wsums[32];
    const int tid = threadIdx.x;
    const int i = blockIdx.x * 1024 + tid;
    const int v = g_deg[i];
    int x = v;
    #pragma unroll
    for (int o = 1; o < 32; o <<= 1) {
        int t = __shfl_up_sync(0xFFFFFFFFu, x, o);
        if ((tid & 31) >= o) x += t;
    }
    if ((tid & 31) == 31) wsums[tid >> 5] = x;
    __syncthreads();
    if (tid < 32) {
        int y = wsums[tid];
        #pragma unroll
        for (int o = 1; o < 32; o <<= 1) {
            int t = __shfl_up_sync(0xFFFFFFFFu, y, o);
            if (tid >= o) y += t;
        }
        wsums[tid] = y;
    }
    __syncthreads();
    const int warp = tid >> 5;
    const int base = warp ? wsums[warp - 1] : 0;
    g_off[i] = base + x - v;
    if (tid == 1023) g_bsum[blockIdx.x] = wsums[31];
}
__global__ void scan2_kernel() {   // 1 block, 64 threads
    __shared__ int s0;
    const int tid = threadIdx.x;
    const int v = g_bsum[tid];
    int x = v;
    #pragma unroll
    for (int o = 1; o < 32; o <<= 1) {
        int t = __shfl_up_sync(0xFFFFFFFFu, x, o);
        if ((tid & 31) >= o) x += t;
    }
    if (tid == 31) s0 = x;
    __syncthreads();
    const int add = (tid >= 32) ? s0 : 0;
    g_boff[tid] = add + x - v;
}
__global__ void scan3_kernel() {   // 64 blocks x 1024
    const int i = blockIdx.x * 1024 + threadIdx.x;
    g_off[i] += g_boff[blockIdx.x];
    if (i == 0) g_off[N_NODES] = E_EDGES;
}
__global__ void fill_csr_kernel(const int* __restrict__ erow,
                                const int* __restrict__ ecol,
                                const float* __restrict__ ew) {
    int e = blockIdx.x * blockDim.x + threadIdx.x;
    if (e < E_EDGES) {
        int r = erow[e];
        int p = g_off[r] + atomicAdd(&g_cur[r], 1);
        g_edges[p] = make_int2(ecol[e], __float_as_int(0.9f * ew[e]));
    }
}

// ======================= propagation (one warp per node) =======================
__global__ void prop_kernel(const float* __restrict__ src,
                            const float* __restrict__ h0,
                            float* __restrict__ dst) {
    const int gw   = (blockIdx.x * blockDim.x + threadIdx.x) >> 5;
    const int lane = threadIdx.x & 31;
    if (gw >= N_NODES) return;
    const int s = g_off[gw];
    const int e = g_off[gw + 1];
    const int half = lane >> 4;
    const int fq   = lane & 15;

    float4 a = make_float4(0.f, 0.f, 0.f, 0.f);
    for (int i = s; i < e; i += 2) {
        const int2 e0 = __ldg(&g_edges[i]);
        int2 e1;
        if (i + 1 < e) e1 = __ldg(&g_edges[i + 1]);
        else           e1 = make_int2(e0.x, 0);
        const int   col = half ? e1.x : e0.x;
        const float w   = __int_as_float(half ? e1.y : e0.y);
        const float4 v  = __ldg((const float4*)(src + ((size_t)col << 6)) + fq);
        a.x = fmaf(w, v.x, a.x);
        a.y = fmaf(w, v.y, a.y);
        a.z = fmaf(w, v.z, a.z);
        a.w = fmaf(w, v.w, a.w);
    }
    a.x += __shfl_xor_sync(0xFFFFFFFFu, a.x, 16);
    a.y += __shfl_xor_sync(0xFFFFFFFFu, a.y, 16);
    a.z += __shfl_xor_sync(0xFFFFFFFFu, a.z, 16);
    a.w += __shfl_xor_sync(0xFFFFFFFFu, a.w, 16);
    if (lane < 16) {
        const float4 hv = __ldg((const float4*)(h0 + ((size_t)gw << 6)) + fq);
        float4 o;
        o.x = fmaf(ALPHA_C, hv.x, a.x);
        o.y = fmaf(ALPHA_C, hv.y, a.y);
        o.z = fmaf(ALPHA_C, hv.z, a.z);
        o.w = fmaf(ALPHA_C, hv.w, a.w);
        ((float4*)(dst + ((size_t)gw << 6)))[fq] = o;
    }
}

// ======================= launch =======================
extern "C" void kernel_launch(void* const* d_in, const int* in_sizes, int n_in,
                              void* d_out, int out_size) {
    const float* x  = (const float*)d_in[0];
    const float* W1 = (const float*)d_in[1];
    const float* b1 = (const float*)d_in[2];
    const float* W2 = (const float*)d_in[3];
    const float* b2 = (const float*)d_in[4];
    const float* W3 = (const float*)d_in[5];
    const float* b3 = (const float*)d_in[6];
    const float* ew = (const float*)d_in[7];
    const int*   er = (const int*)d_in[8];
    const int*   ec = (const int*)d_in[9];
    float* out = (float*)d_out;

    float *h0, *ha;
    __nv_bfloat16 *x2, *h1s, *h2s, *B1h, *B1l, *B2h, *B2l, *B3h, *B3l;
    cudaGetSymbolAddress((void**)&h0,  g_h0);
    cudaGetSymbolAddress((void**)&ha,  g_ha);
    cudaGetSymbolAddress((void**)&x2,  g_x2);
    cudaGetSymbolAddress((void**)&h1s, g_h1s);
    cudaGetSymbolAddress((void**)&h2s, g_h2s);
    cudaGetSymbolAddress((void**)&B1h, g_B1h);
    cudaGetSymbolAddress((void**)&B1l, g_B1l);
    cudaGetSymbolAddress((void**)&B2h, g_B2h);
    cudaGetSymbolAddress((void**)&B2l, g_B2l);
    cudaGetSymbolAddress((void**)&B3h, g_B3h);
    cudaGetSymbolAddress((void**)&B3l, g_B3l);

    constexpr int SMEM_BN128 = 2 * (128 * 128 + 2 * 128 * 128);  // 98304
    constexpr int SMEM_BN64  = 2 * (128 * 128 + 2 * 64 * 128);   // 65536

    static cudaStream_t s2;
    static cudaEvent_t evF, evJ;
    static bool inited = false;
    if (!inited) {
        cudaStreamCreateWithFlags(&s2, cudaStreamNonBlocking);
        cudaEventCreateWithFlags(&evF, cudaEventDisableTiming);
        cudaEventCreateWithFlags(&evJ, cudaEventDisableTiming);
        cudaFuncSetAttribute(mma_gemm_kernel<128, 512, 1024, true,  true,  256>,
                             cudaFuncAttributeMaxDynamicSharedMemorySize, SMEM_BN128);
        cudaFuncSetAttribute(mma_gemm_kernel<128, 256, 512,  true,  true,  256>,
                             cudaFuncAttributeMaxDynamicSharedMemorySize, SMEM_BN128);
        cudaFuncSetAttribute(mma_gemm_kernel<64,  256, 512,  false, false, 64>,
                             cudaFuncAttributeMaxDynamicSharedMemorySize, SMEM_BN64);
        inited = true;
    }

    // ---- fork: CSR chain on side stream, overlapped with conv + GEMMs ----
    cudaEventRecord(evF, 0);
    cudaStreamWaitEvent(s2, evF, 0);

    zero_counts_kernel<<<N_NODES / 256, 256, 0, s2>>>();
    count_deg_kernel<<<E_EDGES / 256, 256, 0, s2>>>(er);
    scan1_kernel<<<64, 1024, 0, s2>>>();
    scan2_kernel<<<1, 64, 0, s2>>>();
    scan3_kernel<<<64, 1024, 0, s2>>>();
    fill_csr_kernel<<<E_EDGES / 256, 256, 0, s2>>>(er, ec, ew);
    cudaEventRecord(evJ, s2);

    // ---- main stream: conversions + MLP ----
    conv_x_kernel<<<(N_NODES * 64) / 256, 256>>>(x);
    conv_w_all_kernel<<<(212992 + 255) / 256, 256>>>(W1, W2, W3);

    mma_gemm_kernel<128, 512, 1024, true,  true,  256>
        <<<dim3(2, N_NODES / 128), 256, SMEM_BN128>>>(x2,  B1h, B1l, b1, h1s);
    mma_gemm_kernel<128, 256, 512,  true,  true,  256>
        <<<dim3(2, N_NODES / 128), 256, SMEM_BN128>>>(h1s, B2h, B2l, b2, h2s);
    mma_gemm_kernel<64,  256, 512,  false, false, 64>
        <<<dim3(1, N_NODES / 128), 256, SMEM_BN64>>>(h2s, B3h, B3l, b3, h0);

    // ---- join, then K=10 propagation steps (one warp per node) ----
    cudaStreamWaitEvent(0, evJ, 0);
    const float* src = h0;
    for (int s = 0; s < K_STEPS; s++) {
        float* dst = (s % 2 == 0) ? ha : out;
        prop_kernel<<<N_NODES / 8, 256>>>(src, h0, dst);
        src = dst;
    }
}